// round 2
// baseline (speedup 1.0000x reference)
#include <cuda_runtime.h>

#define TOTAL_ELEMS 16777216   // 16 * 8 * 64 * 2048
#define NV (TOTAL_ELEMS / 4)   // float4 vectors
#define NBLK 1184              // ~8 CTAs per SM on 148-SM B200
#define NTHR 256

// Deterministic block-partial scratch (no device-side allocation allowed).
__device__ float g_part[NBLK * 4];

__global__ __launch_bounds__(NTHR) void attnloss_partial_kernel(
    const float* __restrict__ x,
    const float* __restrict__ attn,
    const float* __restrict__ noise,
    const int* __restrict__ mask,    // bool promoted to 4-byte elements
    const int* __restrict__ pB1, const int* __restrict__ pT1,
    const int* __restrict__ pC1, const int* __restrict__ pP1,
    const int* __restrict__ pB2, const int* __restrict__ pT2,
    const int* __restrict__ pC2, const int* __restrict__ pP2,
    const int* __restrict__ pB3, const int* __restrict__ pT3,
    const int* __restrict__ pC3, const int* __restrict__ pP3)
{
    float s0 = 0.f, s1 = 0.f, s2 = 0.f, s3 = 0.f;
    const int stride = gridDim.x * blockDim.x;

    for (int v = blockIdx.x * blockDim.x + threadIdx.x; v < NV; v += stride) {
        const int i = v << 2;           // element index of lane 0
        const int p = i & 2047;         // P = 2048
        const int c = (i >> 11) & 63;   // C = 64
        const int t = (i >> 17) & 7;    // T = 8
        const int b = i >> 20;          // B = 16

        const float4 x4 = __ldg((const float4*)x + v);
        const float4 a4 = __ldg((const float4*)attn + v);
        const float4 n4 = __ldg((const float4*)noise + v);
        const int4  m4 = __ldg((const int4*)mask + v);   // one 32-bit word per element

        // loss_pos: (x - x_pos)^2 = noise^2 where mask, else 0
        // (nonzero test is correct whether bool was promoted to int32 or float32)
        s0 += (m4.x ? a4.x * n4.x * n4.x : 0.f)
            + (m4.y ? a4.y * n4.y * n4.y : 0.f)
            + (m4.z ? a4.z * n4.z * n4.z : 0.f)
            + (m4.w ? a4.w * n4.w * n4.w : 0.f);

        const int vp = p >> 2;  // pP[p..p+3] is int4-aligned (p % 4 == 0)
        float d;

        {   // neg 1
            const int rb = ((((__ldg(pB1 + b) << 3) + __ldg(pT1 + t)) << 6)
                            + __ldg(pC1 + c)) << 11;
            const int4 pp = __ldg((const int4*)pP1 + vp);
            d = x4.x - __ldg(x + rb + pp.x); s1 += a4.x * d * d;
            d = x4.y - __ldg(x + rb + pp.y); s1 += a4.y * d * d;
            d = x4.z - __ldg(x + rb + pp.z); s1 += a4.z * d * d;
            d = x4.w - __ldg(x + rb + pp.w); s1 += a4.w * d * d;
        }
        {   // neg 2
            const int rb = ((((__ldg(pB2 + b) << 3) + __ldg(pT2 + t)) << 6)
                            + __ldg(pC2 + c)) << 11;
            const int4 pp = __ldg((const int4*)pP2 + vp);
            d = x4.x - __ldg(x + rb + pp.x); s2 += a4.x * d * d;
            d = x4.y - __ldg(x + rb + pp.y); s2 += a4.y * d * d;
            d = x4.z - __ldg(x + rb + pp.z); s2 += a4.z * d * d;
            d = x4.w - __ldg(x + rb + pp.w); s2 += a4.w * d * d;
        }
        {   // neg 3
            const int rb = ((((__ldg(pB3 + b) << 3) + __ldg(pT3 + t)) << 6)
                            + __ldg(pC3 + c)) << 11;
            const int4 pp = __ldg((const int4*)pP3 + vp);
            d = x4.x - __ldg(x + rb + pp.x); s3 += a4.x * d * d;
            d = x4.y - __ldg(x + rb + pp.y); s3 += a4.y * d * d;
            d = x4.z - __ldg(x + rb + pp.z); s3 += a4.z * d * d;
            d = x4.w - __ldg(x + rb + pp.w); s3 += a4.w * d * d;
        }
    }

    // Warp reduce (deterministic tree)
    #pragma unroll
    for (int o = 16; o > 0; o >>= 1) {
        s0 += __shfl_down_sync(0xffffffffu, s0, o);
        s1 += __shfl_down_sync(0xffffffffu, s1, o);
        s2 += __shfl_down_sync(0xffffffffu, s2, o);
        s3 += __shfl_down_sync(0xffffffffu, s3, o);
    }

    __shared__ float sh[4][NTHR / 32];
    const int w = threadIdx.x >> 5;
    if ((threadIdx.x & 31) == 0) {
        sh[0][w] = s0; sh[1][w] = s1; sh[2][w] = s2; sh[3][w] = s3;
    }
    __syncthreads();

    if (threadIdx.x == 0) {
        float t0 = 0.f, t1 = 0.f, t2 = 0.f, t3 = 0.f;
        #pragma unroll
        for (int k = 0; k < NTHR / 32; k++) {
            t0 += sh[0][k]; t1 += sh[1][k]; t2 += sh[2][k]; t3 += sh[3][k];
        }
        g_part[blockIdx.x * 4 + 0] = t0;
        g_part[blockIdx.x * 4 + 1] = t1;
        g_part[blockIdx.x * 4 + 2] = t2;
        g_part[blockIdx.x * 4 + 3] = t3;
    }
}

__global__ __launch_bounds__(NTHR) void attnloss_final_kernel(float* __restrict__ out)
{
    float s0 = 0.f, s1 = 0.f, s2 = 0.f, s3 = 0.f;
    for (int k = threadIdx.x; k < NBLK; k += NTHR) {
        s0 += g_part[k * 4 + 0];
        s1 += g_part[k * 4 + 1];
        s2 += g_part[k * 4 + 2];
        s3 += g_part[k * 4 + 3];
    }
    #pragma unroll
    for (int o = 16; o > 0; o >>= 1) {
        s0 += __shfl_down_sync(0xffffffffu, s0, o);
        s1 += __shfl_down_sync(0xffffffffu, s1, o);
        s2 += __shfl_down_sync(0xffffffffu, s2, o);
        s3 += __shfl_down_sync(0xffffffffu, s3, o);
    }
    __shared__ float sh[4][NTHR / 32];
    const int w = threadIdx.x >> 5;
    if ((threadIdx.x & 31) == 0) {
        sh[0][w] = s0; sh[1][w] = s1; sh[2][w] = s2; sh[3][w] = s3;
    }
    __syncthreads();

    if (threadIdx.x == 0) {
        float t0 = 0.f, t1 = 0.f, t2 = 0.f, t3 = 0.f;
        #pragma unroll
        for (int k = 0; k < NTHR / 32; k++) {
            t0 += sh[0][k]; t1 += sh[1][k]; t2 += sh[2][k]; t3 += sh[3][k];
        }
        const float inv = 1.0f / (float)TOTAL_ELEMS;
        const float pos = t0 * inv;
        const float n1  = t1 * inv;
        const float n2  = t2 * inv;
        const float n3  = t3 * inv;
        // TEMP = 1:  loss = -log(exp(pos) / (exp(n1)+exp(n2)+exp(n3)))
        out[0] = -pos + logf(expf(n1) + expf(n2) + expf(n3));
    }
}

extern "C" void kernel_launch(void* const* d_in, const int* in_sizes, int n_in,
                              void* d_out, int out_size)
{
    const float* x     = (const float*)d_in[0];
    const float* attn  = (const float*)d_in[1];
    const float* noise = (const float*)d_in[2];
    const int*   mask  = (const int*)d_in[3];
    const int* pB1 = (const int*)d_in[4];
    const int* pT1 = (const int*)d_in[5];
    const int* pC1 = (const int*)d_in[6];
    const int* pP1 = (const int*)d_in[7];
    const int* pB2 = (const int*)d_in[8];
    const int* pT2 = (const int*)d_in[9];
    const int* pC2 = (const int*)d_in[10];
    const int* pP2 = (const int*)d_in[11];
    const int* pB3 = (const int*)d_in[12];
    const int* pT3 = (const int*)d_in[13];
    const int* pC3 = (const int*)d_in[14];
    const int* pP3 = (const int*)d_in[15];

    attnloss_partial_kernel<<<NBLK, NTHR>>>(
        x, attn, noise, mask,
        pB1, pT1, pC1, pP1,
        pB2, pT2, pC2, pP2,
        pB3, pT3, pC3, pP3);
    attnloss_final_kernel<<<1, NTHR>>>((float*)d_out);
}

// round 5
// speedup vs baseline: 1.3209x; 1.3209x over previous
#include <cuda_runtime.h>

#define B_DIM 16
#define T_DIM 8
#define C_DIM 64
#define P_DIM 2048
#define ROWS  (B_DIM * T_DIM * C_DIM)     // 8192 destination rows
#define TOTAL_ELEMS (ROWS * P_DIM)        // 16777216
#define NTHR 256
#define VROW (P_DIM / 4)                  // 512 float4 per row

// Block partials (float4 per destination row). No device-side allocation.
__device__ float4 g_part[ROWS];

__global__ __launch_bounds__(NTHR) void attnloss_partial_kernel(
    const float* __restrict__ x,
    const float* __restrict__ attn,
    const float* __restrict__ noise,
    const int* __restrict__ mask,    // bool promoted to 4-byte words
    const int* __restrict__ pB1, const int* __restrict__ pT1,
    const int* __restrict__ pC1, const int* __restrict__ pP1,
    const int* __restrict__ pB2, const int* __restrict__ pT2,
    const int* __restrict__ pC2, const int* __restrict__ pP2,
    const int* __restrict__ pB3, const int* __restrict__ pT3,
    const int* __restrict__ pC3, const int* __restrict__ pP3)
{
    __shared__ float sm[3 * P_DIM];          // 24 KB: three source rows
    float* const sm1 = sm;
    float* const sm2 = sm + P_DIM;
    float* const sm3 = sm + 2 * P_DIM;

    const int tid = threadIdx.x;
    const int blk = blockIdx.x;              // destination row id
    const int c = blk & (C_DIM - 1);
    const int t = (blk >> 6) & (T_DIM - 1);
    const int b = blk >> 9;

    // Source row bases (contiguous 8 KB rows of x). 32-bit math: max < 2^24.
    const int rb1 = ((((__ldg(pB1 + b) << 3) + __ldg(pT1 + t)) << 6) + __ldg(pC1 + c)) << 11;
    const int rb2 = ((((__ldg(pB2 + b) << 3) + __ldg(pT2 + t)) << 6) + __ldg(pC2 + c)) << 11;
    const int rb3 = ((((__ldg(pB3 + b) << 3) + __ldg(pT3 + t)) << 6) + __ldg(pC3 + c)) << 11;

    // Coalesced load of the three source rows into SMEM (x stays on L2 path).
    {
        const float4* s1 = (const float4*)(x + rb1);
        const float4* s2 = (const float4*)(x + rb2);
        const float4* s3 = (const float4*)(x + rb3);
        #pragma unroll
        for (int k = tid; k < VROW; k += NTHR) {
            const float4 v1 = __ldg(s1 + k);
            const float4 v2 = __ldg(s2 + k);
            const float4 v3 = __ldg(s3 + k);
            ((float4*)sm1)[k] = v1;
            ((float4*)sm2)[k] = v2;
            ((float4*)sm3)[k] = v3;
        }
    }
    __syncthreads();

    float s0 = 0.f, s1a = 0.f, s2a = 0.f, s3a = 0.f;

    // Each thread: 2 float4 vectors = 8 consecutive elements of the dest row.
    #pragma unroll
    for (int j = 0; j < 2; j++) {
        const int vloc = tid * 2 + j;            // 0..511 within row
        const int gv = (blk << 9) + vloc;        // global float4 index

        const float4 x4 = __ldg((const float4*)x + gv);         // L2-resident
        const float4 a4 = __ldcs((const float4*)attn + gv);     // stream
        const float4 n4 = __ldcs((const float4*)noise + gv);    // stream
        const int4  m4 = __ldcs((const int4*)mask + gv);        // stream
        const int4 pp1 = __ldg((const int4*)pP1 + vloc);        // 8 KB, L2-hot
        const int4 pp2 = __ldg((const int4*)pP2 + vloc);
        const int4 pp3 = __ldg((const int4*)pP3 + vloc);

        s0 += (m4.x ? a4.x * n4.x * n4.x : 0.f)
            + (m4.y ? a4.y * n4.y * n4.y : 0.f)
            + (m4.z ? a4.z * n4.z * n4.z : 0.f)
            + (m4.w ? a4.w * n4.w * n4.w : 0.f);

        float d;
        d = x4.x - sm1[pp1.x]; s1a += a4.x * d * d;
        d = x4.y - sm1[pp1.y]; s1a += a4.y * d * d;
        d = x4.z - sm1[pp1.z]; s1a += a4.z * d * d;
        d = x4.w - sm1[pp1.w]; s1a += a4.w * d * d;

        d = x4.x - sm2[pp2.x]; s2a += a4.x * d * d;
        d = x4.y - sm2[pp2.y]; s2a += a4.y * d * d;
        d = x4.z - sm2[pp2.z]; s2a += a4.z * d * d;
        d = x4.w - sm2[pp2.w]; s2a += a4.w * d * d;

        d = x4.x - sm3[pp3.x]; s3a += a4.x * d * d;
        d = x4.y - sm3[pp3.y]; s3a += a4.y * d * d;
        d = x4.z - sm3[pp3.z]; s3a += a4.z * d * d;
        d = x4.w - sm3[pp3.w]; s3a += a4.w * d * d;
    }

    // Block reduction (deterministic tree)
    #pragma unroll
    for (int o = 16; o > 0; o >>= 1) {
        s0  += __shfl_down_sync(0xffffffffu, s0,  o);
        s1a += __shfl_down_sync(0xffffffffu, s1a, o);
        s2a += __shfl_down_sync(0xffffffffu, s2a, o);
        s3a += __shfl_down_sync(0xffffffffu, s3a, o);
    }
    __shared__ float4 shp[NTHR / 32];
    const int w = tid >> 5;
    if ((tid & 31) == 0) shp[w] = make_float4(s0, s1a, s2a, s3a);
    __syncthreads();

    if (tid == 0) {
        float4 acc = shp[0];
        #pragma unroll
        for (int k = 1; k < NTHR / 32; k++) {
            acc.x += shp[k].x; acc.y += shp[k].y;
            acc.z += shp[k].z; acc.w += shp[k].w;
        }
        g_part[blk] = acc;
    }
}

__global__ __launch_bounds__(NTHR) void attnloss_final_kernel(float* __restrict__ out)
{
    float4 acc = make_float4(0.f, 0.f, 0.f, 0.f);
    for (int k = threadIdx.x; k < ROWS; k += NTHR) {
        const float4 p = g_part[k];
        acc.x += p.x; acc.y += p.y; acc.z += p.z; acc.w += p.w;
    }
    #pragma unroll
    for (int o = 16; o > 0; o >>= 1) {
        acc.x += __shfl_down_sync(0xffffffffu, acc.x, o);
        acc.y += __shfl_down_sync(0xffffffffu, acc.y, o);
        acc.z += __shfl_down_sync(0xffffffffu, acc.z, o);
        acc.w += __shfl_down_sync(0xffffffffu, acc.w, o);
    }
    __shared__ float4 shp[NTHR / 32];
    const int w = threadIdx.x >> 5;
    if ((threadIdx.x & 31) == 0) shp[w] = acc;
    __syncthreads();

    if (threadIdx.x == 0) {
        float4 r = shp[0];
        #pragma unroll
        for (int k = 1; k < NTHR / 32; k++) {
            r.x += shp[k].x; r.y += shp[k].y;
            r.z += shp[k].z; r.w += shp[k].w;
        }
        const float inv = 1.0f / (float)TOTAL_ELEMS;
        const float pos = r.x * inv;
        const float n1  = r.y * inv;
        const float n2  = r.z * inv;
        const float n3  = r.w * inv;
        // TEMP = 1:  loss = -pos + log(exp(n1)+exp(n2)+exp(n3))
        out[0] = -pos + logf(expf(n1) + expf(n2) + expf(n3));
    }
}

extern "C" void kernel_launch(void* const* d_in, const int* in_sizes, int n_in,
                              void* d_out, int out_size)
{
    const float* x     = (const float*)d_in[0];
    const float* attn  = (const float*)d_in[1];
    const float* noise = (const float*)d_in[2];
    const int*   mask  = (const int*)d_in[3];
    const int* pB1 = (const int*)d_in[4];
    const int* pT1 = (const int*)d_in[5];
    const int* pC1 = (const int*)d_in[6];
    const int* pP1 = (const int*)d_in[7];
    const int* pB2 = (const int*)d_in[8];
    const int* pT2 = (const int*)d_in[9];
    const int* pC2 = (const int*)d_in[10];
    const int* pP2 = (const int*)d_in[11];
    const int* pB3 = (const int*)d_in[12];
    const int* pT3 = (const int*)d_in[13];
    const int* pC3 = (const int*)d_in[14];
    const int* pP3 = (const int*)d_in[15];

    attnloss_partial_kernel<<<ROWS, NTHR>>>(
        x, attn, noise, mask,
        pB1, pT1, pC1, pP1,
        pB2, pT2, pC2, pP2,
        pB3, pT3, pC3, pP3);
    attnloss_final_kernel<<<1, NTHR>>>((float*)d_out);
}

// round 6
// speedup vs baseline: 1.7733x; 1.3425x over previous
#include <cuda_runtime.h>
#include <cstdint>

#define B_DIM 16
#define T_DIM 8
#define C_DIM 64
#define P_DIM 2048
#define ROWS  (B_DIM * T_DIM * C_DIM)     // 8192 destination rows
#define TOTAL_ELEMS (ROWS * P_DIM)        // 16777216
#define NTHR 256
#define VROW (P_DIM / 4)                  // 512 float4 per row
#define ROW_BYTES (P_DIM * 4)             // 8192 bytes per row

// Block partials (float4 per destination row). No device-side allocation.
__device__ float4 g_part[ROWS];

__device__ __forceinline__ uint32_t smem_u32(const void* p) {
    uint32_t a;
    asm("{ .reg .u64 t; cvta.to.shared.u64 t, %1; cvt.u32.u64 %0, t; }"
        : "=r"(a) : "l"(p));
    return a;
}

__global__ __launch_bounds__(NTHR) void attnloss_partial_kernel(
    const float* __restrict__ x,
    const float* __restrict__ attn,
    const float* __restrict__ noise,
    const int* __restrict__ mask,    // bool promoted to 4-byte words
    const int* __restrict__ pB1, const int* __restrict__ pT1,
    const int* __restrict__ pC1, const int* __restrict__ pP1,
    const int* __restrict__ pB2, const int* __restrict__ pT2,
    const int* __restrict__ pC2, const int* __restrict__ pP2,
    const int* __restrict__ pB3, const int* __restrict__ pT3,
    const int* __restrict__ pC3, const int* __restrict__ pP3)
{
    __shared__ __align__(128) float sm[3 * P_DIM];   // 24 KB: three source rows
    __shared__ __align__(8) uint64_t mbar;

    float* const sm1 = sm;
    float* const sm2 = sm + P_DIM;
    float* const sm3 = sm + 2 * P_DIM;

    const int tid = threadIdx.x;
    const int blk = blockIdx.x;              // destination row id
    const int c = blk & (C_DIM - 1);
    const int t = (blk >> 6) & (T_DIM - 1);
    const int b = blk >> 9;

    const uint32_t mbar_a = smem_u32(&mbar);

    if (tid == 0) {
        asm volatile("mbarrier.init.shared.b64 [%0], 1;" :: "r"(mbar_a) : "memory");
    }
    __syncthreads();

    if (tid == 0) {
        // Source row bases (contiguous 8 KB rows of x). 32-bit math: max < 2^24.
        const int rb1 = ((((__ldg(pB1 + b) << 3) + __ldg(pT1 + t)) << 6) + __ldg(pC1 + c)) << 11;
        const int rb2 = ((((__ldg(pB2 + b) << 3) + __ldg(pT2 + t)) << 6) + __ldg(pC2 + c)) << 11;
        const int rb3 = ((((__ldg(pB3 + b) << 3) + __ldg(pT3 + t)) << 6) + __ldg(pC3 + c)) << 11;

        asm volatile("mbarrier.arrive.expect_tx.shared.b64 _, [%0], %1;"
                     :: "r"(mbar_a), "r"(3 * ROW_BYTES) : "memory");
        asm volatile("cp.async.bulk.shared::cta.global.mbarrier::complete_tx::bytes [%0], [%1], %2, [%3];"
                     :: "r"(smem_u32(sm1)), "l"(x + rb1), "r"(ROW_BYTES), "r"(mbar_a) : "memory");
        asm volatile("cp.async.bulk.shared::cta.global.mbarrier::complete_tx::bytes [%0], [%1], %2, [%3];"
                     :: "r"(smem_u32(sm2)), "l"(x + rb2), "r"(ROW_BYTES), "r"(mbar_a) : "memory");
        asm volatile("cp.async.bulk.shared::cta.global.mbarrier::complete_tx::bytes [%0], [%1], %2, [%3];"
                     :: "r"(smem_u32(sm3)), "l"(x + rb3), "r"(ROW_BYTES), "r"(mbar_a) : "memory");
    }

    // Prefetch both j-slices of the coalesced streams while the bulk copies fly.
    // vloc = j*256 + tid -> warp-contiguous 512B accesses (fixes R5 stride-32B bug).
    float4 x4[2], a4[2], n4[2];
    int4 m4[2], pp1[2], pp2[2], pp3[2];
    #pragma unroll
    for (int j = 0; j < 2; j++) {
        const int vloc = j * NTHR + tid;         // 0..511 within row
        const int gv = (blk << 9) + vloc;        // global float4 index
        x4[j] = __ldg((const float4*)x + gv);            // L2-resident
        a4[j] = __ldcs((const float4*)attn + gv);        // stream
        n4[j] = __ldcs((const float4*)noise + gv);       // stream
        m4[j] = __ldcs((const int4*)mask + gv);          // stream
        pp1[j] = __ldg((const int4*)pP1 + vloc);         // 8 KB, L2-hot
        pp2[j] = __ldg((const int4*)pP2 + vloc);
        pp3[j] = __ldg((const int4*)pP3 + vloc);
    }

    // Wait for the three source rows (acquire orders the LDS gathers below).
    {
        uint32_t done;
        asm volatile(
            "{\n\t.reg .pred p;\n\t"
            "mbarrier.try_wait.parity.acquire.cta.shared::cta.b64 p, [%1], 0;\n\t"
            "selp.b32 %0, 1, 0, p;\n\t}"
            : "=r"(done) : "r"(mbar_a) : "memory");
        if (!done) {
            asm volatile(
                "{\n\t.reg .pred P1;\n\t"
                "WAIT_LOOP_%=:\n\t"
                "mbarrier.try_wait.parity.acquire.cta.shared::cta.b64 P1, [%0], 0, 0x989680;\n\t"
                "@P1 bra.uni WAIT_DONE_%=;\n\t"
                "bra.uni WAIT_LOOP_%=;\n\t"
                "WAIT_DONE_%=:\n\t}"
                :: "r"(mbar_a) : "memory");
        }
    }

    float s0 = 0.f, s1a = 0.f, s2a = 0.f, s3a = 0.f;

    #pragma unroll
    for (int j = 0; j < 2; j++) {
        s0 += (m4[j].x ? a4[j].x * n4[j].x * n4[j].x : 0.f)
            + (m4[j].y ? a4[j].y * n4[j].y * n4[j].y : 0.f)
            + (m4[j].z ? a4[j].z * n4[j].z * n4[j].z : 0.f)
            + (m4[j].w ? a4[j].w * n4[j].w * n4[j].w : 0.f);

        float d;
        d = x4[j].x - sm1[pp1[j].x]; s1a += a4[j].x * d * d;
        d = x4[j].y - sm1[pp1[j].y]; s1a += a4[j].y * d * d;
        d = x4[j].z - sm1[pp1[j].z]; s1a += a4[j].z * d * d;
        d = x4[j].w - sm1[pp1[j].w]; s1a += a4[j].w * d * d;

        d = x4[j].x - sm2[pp2[j].x]; s2a += a4[j].x * d * d;
        d = x4[j].y - sm2[pp2[j].y]; s2a += a4[j].y * d * d;
        d = x4[j].z - sm2[pp2[j].z]; s2a += a4[j].z * d * d;
        d = x4[j].w - sm2[pp2[j].w]; s2a += a4[j].w * d * d;

        d = x4[j].x - sm3[pp3[j].x]; s3a += a4[j].x * d * d;
        d = x4[j].y - sm3[pp3[j].y]; s3a += a4[j].y * d * d;
        d = x4[j].z - sm3[pp3[j].z]; s3a += a4[j].z * d * d;
        d = x4[j].w - sm3[pp3[j].w]; s3a += a4[j].w * d * d;
    }

    // Block reduction (deterministic tree)
    #pragma unroll
    for (int o = 16; o > 0; o >>= 1) {
        s0  += __shfl_down_sync(0xffffffffu, s0,  o);
        s1a += __shfl_down_sync(0xffffffffu, s1a, o);
        s2a += __shfl_down_sync(0xffffffffu, s2a, o);
        s3a += __shfl_down_sync(0xffffffffu, s3a, o);
    }
    __shared__ float4 shp[NTHR / 32];
    const int w = tid >> 5;
    if ((tid & 31) == 0) shp[w] = make_float4(s0, s1a, s2a, s3a);
    __syncthreads();

    if (tid == 0) {
        float4 acc = shp[0];
        #pragma unroll
        for (int k = 1; k < NTHR / 32; k++) {
            acc.x += shp[k].x; acc.y += shp[k].y;
            acc.z += shp[k].z; acc.w += shp[k].w;
        }
        g_part[blk] = acc;
    }
}

#define FTHR 1024

__global__ __launch_bounds__(FTHR) void attnloss_final_kernel(float* __restrict__ out)
{
    float4 acc = make_float4(0.f, 0.f, 0.f, 0.f);
    // 8192 partials / 1024 threads = 8 each; fully unrolled for MLP.
    #pragma unroll
    for (int u = 0; u < ROWS / FTHR; u++) {
        const float4 p = g_part[u * FTHR + threadIdx.x];
        acc.x += p.x; acc.y += p.y; acc.z += p.z; acc.w += p.w;
    }
    #pragma unroll
    for (int o = 16; o > 0; o >>= 1) {
        acc.x += __shfl_down_sync(0xffffffffu, acc.x, o);
        acc.y += __shfl_down_sync(0xffffffffu, acc.y, o);
        acc.z += __shfl_down_sync(0xffffffffu, acc.z, o);
        acc.w += __shfl_down_sync(0xffffffffu, acc.w, o);
    }
    __shared__ float4 shp[FTHR / 32];
    const int w = threadIdx.x >> 5;
    if ((threadIdx.x & 31) == 0) shp[w] = acc;
    __syncthreads();

    if (threadIdx.x == 0) {
        float4 r = shp[0];
        #pragma unroll
        for (int k = 1; k < FTHR / 32; k++) {
            r.x += shp[k].x; r.y += shp[k].y;
            r.z += shp[k].z; r.w += shp[k].w;
        }
        const float inv = 1.0f / (float)TOTAL_ELEMS;
        const float pos = r.x * inv;
        const float n1  = r.y * inv;
        const float n2  = r.z * inv;
        const float n3  = r.w * inv;
        // TEMP = 1:  loss = -pos + log(exp(n1)+exp(n2)+exp(n3))
        out[0] = -pos + logf(expf(n1) + expf(n2) + expf(n3));
    }
}

extern "C" void kernel_launch(void* const* d_in, const int* in_sizes, int n_in,
                              void* d_out, int out_size)
{
    const float* x     = (const float*)d_in[0];
    const float* attn  = (const float*)d_in[1];
    const float* noise = (const float*)d_in[2];
    const int*   mask  = (const int*)d_in[3];
    const int* pB1 = (const int*)d_in[4];
    const int* pT1 = (const int*)d_in[5];
    const int* pC1 = (const int*)d_in[6];
    const int* pP1 = (const int*)d_in[7];
    const int* pB2 = (const int*)d_in[8];
    const int* pT2 = (const int*)d_in[9];
    const int* pC2 = (const int*)d_in[10];
    const int* pP2 = (const int*)d_in[11];
    const int* pB3 = (const int*)d_in[12];
    const int* pT3 = (const int*)d_in[13];
    const int* pC3 = (const int*)d_in[14];
    const int* pP3 = (const int*)d_in[15];

    attnloss_partial_kernel<<<ROWS, NTHR>>>(
        x, attn, noise, mask,
        pB1, pT1, pC1, pP1,
        pB2, pT2, pC2, pP2,
        pB3, pT3, pC3, pP3);
    attnloss_final_kernel<<<1, FTHR>>>((float*)d_out);
}